// round 3
// baseline (speedup 1.0000x reference)
#include <cuda_runtime.h>
#include <cstdint>
#include <cstddef>

// Problem constants
#define OSIZE 224
#define NB 64
#define HM 512
#define WMETA 513
#define WMC 512          // image width without metadata column

// Per-batch crop params computed by params_kernel
__device__ int g_pi[NB], g_pj[NB], g_ph[NB], g_pw[NB], g_pflip[NB];

// ---------------------------------------------------------------------------
// Threefry-2x32 (JAX-compatible): 20 rounds, key schedule ks2 = k0^k1^parity
// ---------------------------------------------------------------------------
__device__ __forceinline__ void tf2x32(uint32_t k0, uint32_t k1,
                                       uint32_t x0, uint32_t x1,
                                       uint32_t &o0, uint32_t &o1) {
    uint32_t ks2 = k0 ^ k1 ^ 0x1BD11BDAu;
    x0 += k0; x1 += k1;
#define TF_RND(r) { x0 += x1; x1 = (x1 << (r)) | (x1 >> (32 - (r))); x1 ^= x0; }
    TF_RND(13) TF_RND(15) TF_RND(26) TF_RND(6)
    x0 += k1;  x1 += ks2 + 1u;
    TF_RND(17) TF_RND(29) TF_RND(16) TF_RND(24)
    x0 += ks2; x1 += k0 + 2u;
    TF_RND(13) TF_RND(15) TF_RND(26) TF_RND(6)
    x0 += k0;  x1 += k1 + 3u;
    TF_RND(17) TF_RND(29) TF_RND(16) TF_RND(24)
    x0 += k1;  x1 += ks2 + 4u;
    TF_RND(13) TF_RND(15) TF_RND(26) TF_RND(6)
    x0 += ks2; x1 += k0 + 5u;
#undef TF_RND
    o0 = x0; o1 = x1;
}

// Partitionable (foldlike) JAX derivations:
//   split(key, n)[i]            = (o0, o1) of threefry(key, (0, i))
//   fold_in(key, t)             = (o0, o1) of threefry(key, (0, t))
//   random_bits(key,32,(N,))[b] = o0 ^ o1 of threefry(key, (0, b))
// (for bit_width <= 32 the partitionable path XORs the two output halves)
__device__ __forceinline__ uint32_t rbits_part(uint32_t k0, uint32_t k1, int idx) {
    uint32_t o0, o1;
    tf2x32(k0, k1, 0u, (uint32_t)idx, o0, o1);
    return o0 ^ o1;
}

// bits -> [0,1) float, JAX style: (bits>>9 | 0x3f800000) as float - 1
__device__ __forceinline__ float bits_to_unit(uint32_t bits) {
    return __uint_as_float((bits >> 9) | 0x3F800000u) - 1.0f;
}

// ---------------------------------------------------------------------------
// Kernel 1: per-batch RandomResizedCrop params + flip mask (64 threads)
// Parameter-path float math uses _rn intrinsics so results are IEEE RN
// regardless of fast-math / FMA contraction, matching XLA f32 semantics.
// ---------------------------------------------------------------------------
__global__ void params_kernel(const float* __restrict__ x) {
    int b = threadIdx.x;
    if (b >= NB) return;

    // root key(42) = (0,42); split -> kflip = tf(key,(0,0)), kparams = tf(key,(0,1))
    uint32_t kf0, kf1, kp0, kp1;
    tf2x32(0u, 42u, 0u, 0u, kf0, kf1);
    tf2x32(0u, 42u, 0u, 1u, kp0, kp1);

    // H, W metadata (integer-valued floats)
    const size_t img_stride = (size_t)3 * HM * WMETA;
    float Hf = x[(size_t)b * img_stride + 512];                      // x[b,0,0,-1]
    float Wf = x[(size_t)b * img_stride + (size_t)HM * WMETA + 512]; // x[b,1,0,-1]

    int flip = bits_to_unit(rbits_part(kf0, kf1, b)) > 0.5f;

    float area = __fmul_rn(Hf, Wf);
    const float lg_lo = -0.22314355131420976f;  // float32(log(0.8))
    const float lg_hi =  0.22314355131420976f;  // float32(log(1.25))

    float fi = 0.f, fj = 0.f, fh = 0.f, fw = 0.f;
    bool succ = false;

    for (int t = 0; t < 10; t++) {
        // fold_in(kparams, t) = threefry(kparams, (0, t))
        uint32_t kt0, kt1;
        tf2x32(kp0, kp1, 0u, (uint32_t)t, kt0, kt1);
        // split(kt, 4)[m] = threefry(kt, (0, m))
        uint32_t ka0, ka1, kb0, kb1, kc0, kc1, kd0, kd1;
        tf2x32(kt0, kt1, 0u, 0u, ka0, ka1);  // k1: target_area
        tf2x32(kt0, kt1, 0u, 1u, kb0, kb1);  // k2: aspect
        tf2x32(kt0, kt1, 0u, 2u, kc0, kc1);  // k3: rand_i
        tf2x32(kt0, kt1, 0u, 3u, kd0, kd1);  // k4: rand_j

        float u1 = bits_to_unit(rbits_part(ka0, ka1, b));
        u1 = fmaxf(0.1f, __fadd_rn(__fmul_rn(u1, 1.0f - 0.1f), 0.1f));
        float u2 = bits_to_unit(rbits_part(kb0, kb1, b));
        u2 = fmaxf(lg_lo, __fadd_rn(__fmul_rn(u2, lg_hi - lg_lo), lg_lo));

        float ta = __fmul_rn(area, u1);
        float aspect = expf(u2);   // libdevice __nv_expf
        float cw = rintf(__fsqrt_rn(__fmul_rn(ta, aspect)));
        float ch = rintf(__fsqrt_rn(__fdiv_rn(ta, aspect)));

        bool valid = (cw > 0.0f) && (cw <= Wf) && (ch > 0.0f) && (ch <= Hf) && !succ;

        float max_i = fmaxf(__fadd_rn(__fsub_rn(Hf, ch), 1.0f), 1.0f);
        float max_j = fmaxf(__fadd_rn(__fsub_rn(Wf, cw), 1.0f), 1.0f);
        float u3 = bits_to_unit(rbits_part(kc0, kc1, b));  // minval=0, maxval=1
        float u4 = bits_to_unit(rbits_part(kd0, kd1, b));
        float ri = floorf(__fmul_rn(u3, max_i));
        float rj = floorf(__fmul_rn(u4, max_j));

        if (valid) { fh = ch; fw = cw; fi = ri; fj = rj; succ = true; }
    }

    if (!succ) {
        float in_ratio = __fdiv_rn(Wf, Hf);
        float fbw = (in_ratio > 1.25f) ? rintf(__fmul_rn(Hf, 1.25f)) : Wf;
        float fbh = (in_ratio < 0.8f)  ? rintf(__fdiv_rn(Wf, 0.8f))  : Hf;
        fi = floorf(__fdiv_rn(__fsub_rn(Hf, fbh), 2.0f));
        fj = floorf(__fdiv_rn(__fsub_rn(Wf, fbw), 2.0f));
        fh = fbh; fw = fbw;
    }

    g_pi[b] = (int)fi; g_pj[b] = (int)fj;
    g_ph[b] = (int)fh; g_pw[b] = (int)fw;
    g_pflip[b] = flip;
}

// ---------------------------------------------------------------------------
// Kernel 2: flip + crop + bilinear resize to 224x224.
// One block per (b, oy); 224 threads = 7 warps, each thread one ox, 3 channels.
// ---------------------------------------------------------------------------
__global__ void __launch_bounds__(OSIZE)
resize_kernel(const float* __restrict__ x, float* __restrict__ out) {
    int ox = threadIdx.x;       // 0..223
    int oy = blockIdx.x;        // 0..223
    int b  = blockIdx.y;        // 0..63

    int ci = g_pi[b], cj = g_pj[b], ch = g_ph[b], cw = g_pw[b];
    int flip = g_pflip[b];
    float hf = (float)ch, wf = (float)cw;

    // y mapping (align_corners=False), IEEE ops so floor boundaries match XLA
    float ysv = __fsub_rn(__fdiv_rn(__fmul_rn((float)oy + 0.5f, hf), 224.0f), 0.5f);
    ysv = fminf(fmaxf(ysv, 0.0f), hf - 1.0f);
    float y0f = floorf(ysv);
    float wy = ysv - y0f;
    int y0 = min(max((int)y0f + ci, 0), HM - 1);
    int ytop = min(max(ci + ch - 1, 0), HM - 1);
    int y1 = min(max(y0 + 1, 0), ytop);

    // x mapping
    float xsv = __fsub_rn(__fdiv_rn(__fmul_rn((float)ox + 0.5f, wf), 224.0f), 0.5f);
    xsv = fminf(fmaxf(xsv, 0.0f), wf - 1.0f);
    float x0f = floorf(xsv);
    float wx = xsv - x0f;
    int x0 = min(max((int)x0f + cj, 0), WMC - 1);
    int xtop = min(max(cj + cw - 1, 0), WMC - 1);
    int x1 = min(max(x0 + 1, 0), xtop);

    // flip: x_no_meta (flipped)[xc] == orig[512 - xc]
    if (flip) { x0 = WMC - x0; x1 = WMC - x1; }

    const float* base = x + (size_t)b * 3 * HM * WMETA;
    size_t r0 = (size_t)y0 * WMETA;
    size_t r1 = (size_t)y1 * WMETA;
    float omwx = 1.0f - wx, omwy = 1.0f - wy;

#pragma unroll
    for (int c = 0; c < 3; c++) {
        const float* img = base + (size_t)c * HM * WMETA;
        float g00 = __ldg(img + r0 + x0);
        float g01 = __ldg(img + r0 + x1);
        float g10 = __ldg(img + r1 + x0);
        float g11 = __ldg(img + r1 + x1);
        float top = omwx * g00 + wx * g01;
        float bot = omwx * g10 + wx * g11;
        out[(((size_t)b * 3 + c) * OSIZE + oy) * OSIZE + ox] = omwy * top + wy * bot;
    }
}

extern "C" void kernel_launch(void* const* d_in, const int* in_sizes, int n_in,
                              void* d_out, int out_size) {
    const float* x = (const float*)d_in[0];
    float* out = (float*)d_out;

    params_kernel<<<1, 64>>>(x);
    dim3 grid(OSIZE, NB);
    resize_kernel<<<grid, OSIZE>>>(x, out);
}